// round 1
// baseline (speedup 1.0000x reference)
#include <cuda_runtime.h>

#define T_STEPS 64
#define BATCH   32
#define IDIM    128
#define HDIM    256
#define MROWS   (T_STEPS * BATCH)   // 2048

// ---------------- scratch (__device__ globals; no allocations allowed) ----------------
__device__ float g_ip [MROWS * HDIM];    // input_proj  = x @ w_i2h.T + b_i2h
__device__ float g_xc [MROWS * HDIM];    // x @ w_i2c.T + b_i2c
__device__ float g_ctx[MROWS * HDIM];    // context at ENTRY of step t, row m = t*B + b
__device__ float g_wtv_c2c[HDIM * HDIM]; // transposed-vectorized weights
__device__ float g_wtv_i2h[HDIM * IDIM];
__device__ float g_wtv_i2c[HDIM * IDIM];
__device__ float g_btv    [HDIM * HDIM]; // b_c2t viewed as [i][j], transposed-vec

// ---------------- transpose to [k-block][i*4 + k%4] layout ----------------
// in is [N rows (i)][K cols (k)]; out[(k>>2)*(N*4) + i*4 + (k&3)] = in[i*K + k]
__global__ void tvec_kernel(const float* __restrict__ in, int which, int N, int K) {
    float* out = (which == 0) ? g_wtv_c2c
               : (which == 1) ? g_wtv_i2h
               : (which == 2) ? g_wtv_i2c
               :                g_btv;
    int idx = blockIdx.x * blockDim.x + threadIdx.x;
    if (idx >= N * K) return;
    int i = idx / K;
    int k = idx - i * K;
    out[(k >> 2) * (N * 4) + i * 4 + (k & 3)] = in[idx];
}

// ---------------- ip / xc projections: one block per row m ----------------
__global__ void proj_kernel(const float* __restrict__ x,
                            const float* __restrict__ b_i2h,
                            const float* __restrict__ b_i2c) {
    __shared__ float xs[IDIM];
    int m = blockIdx.x;
    int i = threadIdx.x;
    if (i < IDIM) xs[i] = x[m * IDIM + i];
    __syncthreads();
    float s1 = b_i2h[i];
    float s2 = b_i2c[i];
#pragma unroll
    for (int k4 = 0; k4 < IDIM / 4; k4++) {
        float4 w1 = *(const float4*)&g_wtv_i2h[k4 * (HDIM * 4) + i * 4];
        float4 w2 = *(const float4*)&g_wtv_i2c[k4 * (HDIM * 4) + i * 4];
        float x0 = xs[k4 * 4 + 0], x1 = xs[k4 * 4 + 1];
        float x2 = xs[k4 * 4 + 2], x3 = xs[k4 * 4 + 3];
        s1 += w1.x * x0 + w1.y * x1 + w1.z * x2 + w1.w * x3;
        s2 += w2.x * x0 + w2.y * x1 + w2.z * x2 + w2.w * x3;
    }
    g_ip[m * HDIM + i] = s1;
    g_xc[m * HDIM + i] = s2;
}

// ---------------- bconst[m,i] = sum_j b_c2t[i*H+j] * ip[m,j] -> written straight into d_out ----------------
__global__ void bconst_kernel(float* __restrict__ out) {
    __shared__ float ips[HDIM];
    int m = blockIdx.x;
    int i = threadIdx.x;
    ips[i] = g_ip[m * HDIM + i];
    __syncthreads();
    float s = 0.f;
#pragma unroll 8
    for (int j4 = 0; j4 < HDIM / 4; j4++) {
        float4 w = *(const float4*)&g_btv[j4 * (HDIM * 4) + i * 4];
        s += w.x * ips[j4 * 4 + 0] + w.y * ips[j4 * 4 + 1]
           + w.z * ips[j4 * 4 + 2] + w.w * ips[j4 * 4 + 3];
    }
    out[m * HDIM + i] = s;
}

// ---------------- context trajectory: 32 independent samples, 1 CTA each ----------------
__global__ void ctx_kernel(const float* __restrict__ b_c2c,
                           float* __restrict__ out_ctx_final) {
    __shared__ float cs[HDIM];
    int b = blockIdx.x;
    int i = threadIdx.x;
    const float a = 0.2f;          // DT/TAU, train_alpha=False
    const float one_minus_a = 1.0f - a;
    cs[i] = 0.f;
    __syncthreads();
    for (int t = 0; t < T_STEPS; t++) {
        // store pre-update context (used by the hypernet GEMM for step t)
        g_ctx[(t * BATCH + b) * HDIM + i] = cs[i];
        float s = b_c2c[i] + g_xc[(t * BATCH + b) * HDIM + i];
#pragma unroll 8
        for (int c4 = 0; c4 < HDIM / 4; c4++) {
            float4 w = *(const float4*)&g_wtv_c2c[c4 * (HDIM * 4) + i * 4];
            float4 cv = *(const float4*)&cs[c4 * 4];
            s += w.x * cv.x + w.y * cv.y + w.z * cv.z + w.w * cv.w;
        }
        s = fmaxf(s, 0.f);
        float nc = one_minus_a * cs[i] + a * s;
        __syncthreads();
        cs[i] = nc;
        __syncthreads();
    }
    out_ctx_final[b * HDIM + i] = cs[i];
}

// ---------------- the big GEMM ----------------
// out[m, i] += sum_j ip[m,j] * ( sum_c ctx[m,c] * w_c2t[i*H*H + j*H + c] )
// M = 2048 (rows m = t*B+b), N = 256 (i), K = 65536 ((j,c))
// Tile: 64 (m) x 64 (i) per CTA, 256 threads, 4x4 micro-tile. ctx/ip tiles live in smem
// for the CTA's lifetime; w_c2t streams through a register-prefetched smem chunk.
#define PAD 68
#define GEMM_SMEM_FLOATS (2 * HDIM * PAD + 64 * PAD)
#define GEMM_SMEM_BYTES  (GEMM_SMEM_FLOATS * 4)

__global__ void __launch_bounds__(256, 1)
big_gemm_kernel(const float* __restrict__ w_c2t, float* __restrict__ out) {
    extern __shared__ float sm[];
    float* ctxT = sm;                   // [HDIM c][PAD] of 64 m-values
    float* ipT  = sm + HDIM * PAD;      // [HDIM j][PAD] of 64 m-values
    float* bs   = sm + 2 * HDIM * PAD;  // [64 c][PAD] of 64 n-values

    const int m0 = blockIdx.x * 64;
    const int n0 = blockIdx.y * 64;
    const int tid = threadIdx.x;
    const int tx = tid & 15;            // n-dim, 4 cols each
    const int ty = tid >> 4;            // m-dim, 4 rows each

    // Load ctx/ip tiles, transposed (c-major / j-major) so compute uses LDS.128
    for (int r = tid; r < 64 * (HDIM / 4); r += 256) {
        int m  = r >> 6;        // 0..63
        int c4 = r & 63;        // 0..63
        float4 v = *(const float4*)&g_ctx[(size_t)(m0 + m) * HDIM + c4 * 4];
        ctxT[(c4 * 4 + 0) * PAD + m] = v.x;
        ctxT[(c4 * 4 + 1) * PAD + m] = v.y;
        ctxT[(c4 * 4 + 2) * PAD + m] = v.z;
        ctxT[(c4 * 4 + 3) * PAD + m] = v.w;
        float4 u = *(const float4*)&g_ip[(size_t)(m0 + m) * HDIM + c4 * 4];
        ipT[(c4 * 4 + 0) * PAD + m] = u.x;
        ipT[(c4 * 4 + 1) * PAD + m] = u.y;
        ipT[(c4 * 4 + 2) * PAD + m] = u.z;
        ipT[(c4 * 4 + 3) * PAD + m] = u.w;
    }

    // B-stream loader mapping: each thread owns row n = tid>>2, 16 c-values at c0 = (tid&3)*16
    const int ln  = tid >> 2;
    const int lc0 = (tid & 3) * 16;
    const float* bsrc = w_c2t + (size_t)(n0 + ln) * (HDIM * HDIM);

    float pf[16];
    {   // prefetch (j=0, cc=0)
        const float* p = bsrc + lc0;
#pragma unroll
        for (int q = 0; q < 4; q++) {
            float4 v = *(const float4*)(p + q * 4);
            pf[q * 4 + 0] = v.x; pf[q * 4 + 1] = v.y;
            pf[q * 4 + 2] = v.z; pf[q * 4 + 3] = v.w;
        }
    }

    float acc[16];
#pragma unroll
    for (int i = 0; i < 16; i++) acc[i] = 0.f;

    for (int j = 0; j < HDIM; j++) {
        float acc2[16];
#pragma unroll
        for (int i = 0; i < 16; i++) acc2[i] = 0.f;

        for (int cc = 0; cc < 4; cc++) {
            // commit prefetched chunk to smem (transposed: bs[c][n])
#pragma unroll
            for (int q = 0; q < 16; q++) bs[(lc0 + q) * PAD + ln] = pf[q];
            __syncthreads();

            // prefetch next chunk while computing
            if (!(j == HDIM - 1 && cc == 3)) {
                int nj  = (cc == 3) ? j + 1 : j;
                int ncc = (cc + 1) & 3;
                const float* p = bsrc + (size_t)nj * HDIM + ncc * 64 + lc0;
#pragma unroll
                for (int q = 0; q < 4; q++) {
                    float4 v = *(const float4*)(p + q * 4);
                    pf[q * 4 + 0] = v.x; pf[q * 4 + 1] = v.y;
                    pf[q * 4 + 2] = v.z; pf[q * 4 + 3] = v.w;
                }
            }

            const float* ct = ctxT + (cc * 64) * PAD;
#pragma unroll 8
            for (int c = 0; c < 64; c++) {
                float4 av = *(const float4*)&ct[c * PAD + ty * 4];
                float4 bv = *(const float4*)&bs[c * PAD + tx * 4];
                acc2[0]  += av.x * bv.x; acc2[1]  += av.x * bv.y;
                acc2[2]  += av.x * bv.z; acc2[3]  += av.x * bv.w;
                acc2[4]  += av.y * bv.x; acc2[5]  += av.y * bv.y;
                acc2[6]  += av.y * bv.z; acc2[7]  += av.y * bv.w;
                acc2[8]  += av.z * bv.x; acc2[9]  += av.z * bv.y;
                acc2[10] += av.z * bv.z; acc2[11] += av.z * bv.w;
                acc2[12] += av.w * bv.x; acc2[13] += av.w * bv.y;
                acc2[14] += av.w * bv.z; acc2[15] += av.w * bv.w;
            }
            __syncthreads();
        }

        // fold in the per-(m, j) scalar ip[m, j]
        float4 sA = *(const float4*)&ipT[j * PAD + ty * 4];
#pragma unroll
        for (int ni = 0; ni < 4; ni++) {
            acc[0 * 4 + ni] += sA.x * acc2[0 * 4 + ni];
            acc[1 * 4 + ni] += sA.y * acc2[1 * 4 + ni];
            acc[2 * 4 + ni] += sA.z * acc2[2 * 4 + ni];
            acc[3 * 4 + ni] += sA.w * acc2[3 * 4 + ni];
        }
    }

    // out += acc (out already holds bconst)
#pragma unroll
    for (int mi = 0; mi < 4; mi++) {
        int row = m0 + ty * 4 + mi;
        float4* o = (float4*)&out[(size_t)row * HDIM + n0 + tx * 4];
        float4 v = *o;
        v.x += acc[mi * 4 + 0];
        v.y += acc[mi * 4 + 1];
        v.z += acc[mi * 4 + 2];
        v.w += acc[mi * 4 + 3];
        *o = v;
    }
}

// ---------------- hidden = output[T-1] ----------------
__global__ void copy_hidden_kernel(float* __restrict__ out) {
    int idx = blockIdx.x * blockDim.x + threadIdx.x;   // 0..8191
    out[MROWS * HDIM + idx] = out[(MROWS - BATCH) * HDIM + idx];
}

// ---------------- launch ----------------
extern "C" void kernel_launch(void* const* d_in, const int* in_sizes, int n_in,
                              void* d_out, int out_size) {
    const float* x      = (const float*)d_in[0];
    // d_in[1] = w_i2h, d_in[2] = b_i2h
    const float* w_i2h  = (const float*)d_in[1];
    const float* b_i2h  = (const float*)d_in[2];
    // d_in[3] = w_h2h, d_in[4] = b_h2h  -> provably dead in the reference
    const float* w_i2c  = (const float*)d_in[5];
    const float* b_i2c  = (const float*)d_in[6];
    const float* w_c2c  = (const float*)d_in[7];
    const float* b_c2c  = (const float*)d_in[8];
    const float* w_c2t  = (const float*)d_in[9];
    const float* b_c2t  = (const float*)d_in[10];
    // d_in[11] = num_steps (== 1 in this dataset)
    float* out = (float*)d_out;

    (void)w_i2h; (void)w_i2c; // consumed via tvec below
    (void)in_sizes; (void)n_in; (void)out_size;

    // weight transposes (cheap, every replay — deterministic, graph-capturable)
    tvec_kernel<<<(HDIM * HDIM + 255) / 256, 256>>>(w_c2c, 0, HDIM, HDIM);
    tvec_kernel<<<(HDIM * IDIM + 255) / 256, 256>>>(w_i2h, 1, HDIM, IDIM);
    tvec_kernel<<<(HDIM * IDIM + 255) / 256, 256>>>(w_i2c, 2, HDIM, IDIM);
    tvec_kernel<<<(HDIM * HDIM + 255) / 256, 256>>>(b_c2t, 3, HDIM, HDIM);

    // projections (parallel over all t,b)
    proj_kernel<<<MROWS, HDIM>>>(x, b_i2h, b_i2c);

    // bias-term of transformed, written straight into the output region
    bconst_kernel<<<MROWS, HDIM>>>(out);

    // sequential context trajectory (independent per sample b)
    ctx_kernel<<<BATCH, HDIM>>>(b_c2c, out + MROWS * HDIM + BATCH * HDIM);

    // the 68.7 GFLOP hypernet GEMM
    cudaFuncSetAttribute(big_gemm_kernel,
                         cudaFuncAttributeMaxDynamicSharedMemorySize,
                         GEMM_SMEM_BYTES);
    big_gemm_kernel<<<dim3(MROWS / 64, HDIM / 64), 256, GEMM_SMEM_BYTES>>>(w_c2t, out);

    // hidden = transformed at t = T-1
    copy_hidden_kernel<<<(BATCH * HDIM) / 1024, 1024>>>(out);
}

// round 3
// speedup vs baseline: 3.4721x; 3.4721x over previous
#include <cuda_runtime.h>
#include <cuda_fp16.h>
#include <cstdint>

#define T_STEPS 64
#define BATCH   32
#define IDIM    128
#define HDIM    256
#define MROWS   (T_STEPS * BATCH)   // 2048
#define KTOT    65536               // (j,c) contraction
#define JGROUPS 8
#define CHUNKS  128                 // 32 j x 4 c-blocks per CTA

// ---------------- scratch (__device__ globals; no allocations allowed) ----------------
__device__ float  g_ip [MROWS * HDIM];
__device__ float  g_xc [MROWS * HDIM];
__device__ __half g_iph [MROWS * HDIM];
__device__ __half g_ctxh[MROWS * HDIM];
__device__ float  g_wtv_c2c[HDIM * HDIM];
__device__ float  g_wtv_i2h[HDIM * IDIM];
__device__ float  g_wtv_i2c[HDIM * IDIM];
__device__ float  g_btv    [HDIM * HDIM];
__device__ __half g_bhi[(size_t)HDIM * KTOT];   // pre-swizzled 64-k chunk images
__device__ __half g_blo[(size_t)HDIM * KTOT];
__device__ float  g_part[(size_t)JGROUPS * MROWS * HDIM];

// ---------------- small PTX helpers (base ISA only — no "a" features) ----------------
__device__ __forceinline__ uint32_t smem_u32(const void* p) {
    uint32_t a;
    asm("{ .reg .u64 t; cvta.to.shared.u64 t, %1; cvt.u32.u64 %0, t; }" : "=r"(a) : "l"(p));
    return a;
}
__device__ __forceinline__ void cp16(uint32_t dst, const void* src) {
    asm volatile("cp.async.cg.shared.global [%0], [%1], 16;" :: "r"(dst), "l"(src));
}
#define CP_COMMIT() asm volatile("cp.async.commit_group;" ::: "memory")
#define CP_WAIT0()  asm volatile("cp.async.wait_group 0;" ::: "memory")

__device__ __forceinline__ void ldsm_x4(uint32_t* r, uint32_t addr) {
    asm volatile("ldmatrix.sync.aligned.m8n8.x4.shared.b16 {%0,%1,%2,%3}, [%4];"
                 : "=r"(r[0]), "=r"(r[1]), "=r"(r[2]), "=r"(r[3]) : "r"(addr));
}
__device__ __forceinline__ void ldsm_x4t(uint32_t* r, uint32_t addr) {
    asm volatile("ldmatrix.sync.aligned.m8n8.x4.trans.shared.b16 {%0,%1,%2,%3}, [%4];"
                 : "=r"(r[0]), "=r"(r[1]), "=r"(r[2]), "=r"(r[3]) : "r"(addr));
}
__device__ __forceinline__ void mma16816(float* d, const uint32_t* a,
                                         uint32_t b0, uint32_t b1) {
    asm volatile(
        "mma.sync.aligned.m16n8k16.row.col.f32.f16.f16.f32 "
        "{%0,%1,%2,%3},{%4,%5,%6,%7},{%8,%9},{%0,%1,%2,%3};"
        : "+f"(d[0]), "+f"(d[1]), "+f"(d[2]), "+f"(d[3])
        : "r"(a[0]), "r"(a[1]), "r"(a[2]), "r"(a[3]), "r"(b0), "r"(b1));
}
__device__ __forceinline__ uint32_t pkh(__half a, __half b) {
    __half2 p = __halves2half2(a, b);
    return *(uint32_t*)&p;
}

// ---------------- transpose to [k-block][i*4 + k%4] layout (for SIMT kernels) -------
__global__ void tvec_kernel(const float* __restrict__ in, int which, int N, int K) {
    float* out = (which == 0) ? g_wtv_c2c
               : (which == 1) ? g_wtv_i2h
               : (which == 2) ? g_wtv_i2c
               :                g_btv;
    int idx = blockIdx.x * blockDim.x + threadIdx.x;
    if (idx >= N * K) return;
    int i = idx / K;
    int k = idx - i * K;
    out[(k >> 2) * (N * 4) + i * 4 + (k & 3)] = in[idx];
}

// ---------------- fp16 hi/lo split of w_c2t into pre-swizzled chunk images ----------
// Chunk kc = j*4+cb holds B_chunk[c=0..63][i=0..255] fp16 (32 KB), laid out so the GEMM
// smem copy is a flat memcpy and ldmatrix.trans reads are conflict-free:
//   phys(c,i) = c*512 + (((i>>3) ^ (c&7)) << 4) + (i&7)*2
__global__ void bsplit_kernel(const float* __restrict__ w) {
    extern __shared__ float s[];                // [256][65]
    int kc = blockIdx.x;                        // 0..1023
    int j = kc >> 2, cb = kc & 3;
    int base = j * 256 + cb * 64;
    int tid = threadIdx.x;
    for (int u = tid; u < 256 * 16; u += 256) {
        int i = u >> 4, f = u & 15;
        float4 v = *(const float4*)(w + (size_t)i * KTOT + base + f * 4);
        s[i * 65 + f * 4 + 0] = v.x;
        s[i * 65 + f * 4 + 1] = v.y;
        s[i * 65 + f * 4 + 2] = v.z;
        s[i * 65 + f * 4 + 3] = v.w;
    }
    __syncthreads();
    char* oh = (char*)(g_bhi + (size_t)kc * 16384);
    char* ol = (char*)(g_blo + (size_t)kc * 16384);
#pragma unroll
    for (int it = 0; it < 8; it++) {
        int u = tid + it * 256;
        int c = u >> 5, ib = u & 31;
        uint32_t ph[4], pl[4];
#pragma unroll
        for (int e = 0; e < 4; e++) {
            float w0 = s[(ib * 8 + 2 * e + 0) * 65 + c];
            float w1 = s[(ib * 8 + 2 * e + 1) * 65 + c];
            __half h0 = __float2half_rn(w0), h1 = __float2half_rn(w1);
            __half l0 = __float2half_rn(w0 - __half2float(h0));
            __half l1 = __float2half_rn(w1 - __half2float(h1));
            ph[e] = pkh(h0, h1);
            pl[e] = pkh(l0, l1);
        }
        uint32_t off = c * 512 + ((ib ^ (c & 7)) << 4);
        *(uint4*)(oh + off) = make_uint4(ph[0], ph[1], ph[2], ph[3]);
        *(uint4*)(ol + off) = make_uint4(pl[0], pl[1], pl[2], pl[3]);
    }
}

// ---------------- ip / xc projections (+ fp16 image of ip) ----------------
__global__ void proj_kernel(const float* __restrict__ x,
                            const float* __restrict__ b_i2h,
                            const float* __restrict__ b_i2c) {
    __shared__ float xs[IDIM];
    int m = blockIdx.x;
    int i = threadIdx.x;
    if (i < IDIM) xs[i] = x[m * IDIM + i];
    __syncthreads();
    float s1 = b_i2h[i];
    float s2 = b_i2c[i];
#pragma unroll
    for (int k4 = 0; k4 < IDIM / 4; k4++) {
        float4 w1 = *(const float4*)&g_wtv_i2h[k4 * (HDIM * 4) + i * 4];
        float4 w2 = *(const float4*)&g_wtv_i2c[k4 * (HDIM * 4) + i * 4];
        float x0 = xs[k4 * 4 + 0], x1 = xs[k4 * 4 + 1];
        float x2 = xs[k4 * 4 + 2], x3 = xs[k4 * 4 + 3];
        s1 += w1.x * x0 + w1.y * x1 + w1.z * x2 + w1.w * x3;
        s2 += w2.x * x0 + w2.y * x1 + w2.z * x2 + w2.w * x3;
    }
    g_ip [m * HDIM + i] = s1;
    g_iph[m * HDIM + i] = __float2half_rn(s1);
    g_xc [m * HDIM + i] = s2;
}

// ---------------- bconst[m,i] = sum_j b_c2t[i*H+j] * ip[m,j] (exact fp32 -> out) ----
__global__ void bconst_kernel(float* __restrict__ out) {
    __shared__ float ips[HDIM];
    int m = blockIdx.x;
    int i = threadIdx.x;
    ips[i] = g_ip[m * HDIM + i];
    __syncthreads();
    float s = 0.f;
#pragma unroll 8
    for (int j4 = 0; j4 < HDIM / 4; j4++) {
        float4 w = *(const float4*)&g_btv[j4 * (HDIM * 4) + i * 4];
        s += w.x * ips[j4 * 4 + 0] + w.y * ips[j4 * 4 + 1]
           + w.z * ips[j4 * 4 + 2] + w.w * ips[j4 * 4 + 3];
    }
    out[m * HDIM + i] = s;
}

// ---------------- context trajectory (+ fp16 image of pre-update ctx) --------------
__global__ void ctx_kernel(const float* __restrict__ b_c2c,
                           float* __restrict__ out_ctx_final) {
    __shared__ float cs[HDIM];
    int b = blockIdx.x;
    int i = threadIdx.x;
    const float a = 0.2f;
    const float one_minus_a = 1.0f - a;
    cs[i] = 0.f;
    __syncthreads();
    for (int t = 0; t < T_STEPS; t++) {
        g_ctxh[(t * BATCH + b) * HDIM + i] = __float2half_rn(cs[i]);
        float s = b_c2c[i] + g_xc[(t * BATCH + b) * HDIM + i];
#pragma unroll 8
        for (int c4 = 0; c4 < HDIM / 4; c4++) {
            float4 w = *(const float4*)&g_wtv_c2c[c4 * (HDIM * 4) + i * 4];
            float4 cv = *(const float4*)&cs[c4 * 4];
            s += w.x * cv.x + w.y * cv.y + w.z * cv.z + w.w * cv.w;
        }
        s = fmaxf(s, 0.f);
        float nc = one_minus_a * cs[i] + a * s;
        __syncthreads();
        cs[i] = nc;
        __syncthreads();
    }
    out_ctx_final[b * HDIM + i] = cs[i];
}

// ---------------- mma.sync hypernet GEMM ----------------
// out[m,i] = sum_{j,c} (iphi[m,j]*ctxhi[m,c]) * (Whi+Wlo)[i, j*256+c]
// CTA: 128 m x 256 i, j-group of 32 (K=8192), 512 threads (4x4 warps, 32m x 64i each).
// A (fp16) generated on the fly: one __hmul2 per pair. B hi/lo via flat cp.async.
#define A_OFF   0
#define BHI_OFF 16384
#define BLO_OFF 49152
#define STAGE   81920
#define GEMM_SMEM (2 * STAGE)      // 163840 B

// phys addr inside A stage: m*128 + ((c/8 ^ m%8)<<4) + (c%8)*2
// phys addr inside B stage: c*512 + ((i/8 ^ c%8)<<4) + (i%8)*2

__device__ __forceinline__ void produce_chunk(char* sm, uint32_t smb, int s,
                                              int nc, int m0, int jg) {
    uint32_t base_u = smb + s * STAGE;
    char*    base_p = sm + s * STAGE;
    int tid = threadIdx.x;
    int jl = nc >> 2, cb = nc & 3;
    int j = jg * 32 + jl;
    size_t kc = (size_t)(j * 4 + cb) * 16384;   // halves

    const char* srch = (const char*)(g_bhi + kc);
    const char* srcl = (const char*)(g_blo + kc);
#pragma unroll
    for (int it = 0; it < 4; it++) {
        int u = tid + it * 512;
        cp16(base_u + BHI_OFF + u * 16, srch + (size_t)u * 16);
        cp16(base_u + BLO_OFF + u * 16, srcl + (size_t)u * 16);
    }
    CP_COMMIT();

    // A: 128 m x 64 c; thread -> (m = tid/4, 16 c's at q*16)
    int m = tid >> 2, q = tid & 3;
    int row = m0 + m;
    __half2 ip2 = __half2half2(g_iph[row * HDIM + j]);
    const __half2* c2 = (const __half2*)&g_ctxh[row * HDIM + cb * 64 + q * 16];
    uint32_t p[8];
#pragma unroll
    for (int e = 0; e < 8; e++) {
        __half2 r = __hmul2(ip2, c2[e]);
        p[e] = *(uint32_t*)&r;
    }
    char* arow = base_p + A_OFF + m * 128;
    int sw = m & 7;
    *(uint4*)(arow + (((q * 2 + 0) ^ sw) << 4)) = make_uint4(p[0], p[1], p[2], p[3]);
    *(uint4*)(arow + (((q * 2 + 1) ^ sw) << 4)) = make_uint4(p[4], p[5], p[6], p[7]);
}

__global__ void __launch_bounds__(512, 1)
hyper_kernel() {
    extern __shared__ char sm[];
    uint32_t smb = smem_u32(sm);
    int tid = threadIdx.x;
    int lane = tid & 31, wid = tid >> 5;
    int warp_m = wid >> 2, warp_i = wid & 3;     // 4 x 4
    int mb = warp_m * 32, ib = warp_i * 64;
    const int m0 = blockIdx.x * 128;
    const int jg = blockIdx.y;

    float acc[2][8][4];
#pragma unroll
    for (int a = 0; a < 2; a++)
#pragma unroll
        for (int b = 0; b < 8; b++)
#pragma unroll
            for (int c = 0; c < 4; c++) acc[a][b][c] = 0.f;

    // per-lane ldmatrix address components
    int lr  = lane & 7;
    int l8  = lane & 8;                 // +8 row for sub-matrices 1,3
    int l16 = (lane & 16) ? 8 : 0;      // +8 col for sub-matrices 2,3

    produce_chunk(sm, smb, 0, 0, m0, jg);
    CP_WAIT0();
    __syncthreads();

    for (int nc = 0; nc < CHUNKS; nc++) {
        int s = nc & 1;
        if (nc + 1 < CHUNKS) produce_chunk(sm, smb, s ^ 1, nc + 1, m0, jg);

        uint32_t Ab = smb + s * STAGE + A_OFF;
        uint32_t Bh = smb + s * STAGE + BHI_OFF;
        uint32_t Bl = smb + s * STAGE + BLO_OFF;

#pragma unroll
        for (int kt = 0; kt < 64; kt += 16) {
            // A fragments: 2 x (m16 k16)
            uint32_t a[2][4];
#pragma unroll
            for (int mi = 0; mi < 2; mi++) {
                int mrow = mb + mi * 16 + lr + l8;
                uint32_t ad = Ab + mrow * 128 + (((((kt + l16) >> 3)) ^ (mrow & 7)) << 4);
                ldsm_x4(a[mi], ad);
            }
            uint32_t b[16];
            // B hi fragments + mma
#pragma unroll
            for (int t = 0; t < 4; t++) {
                int c = kt + lr + l8;
                int iu = (ib + t * 16 + l16) >> 3;
                ldsm_x4t(&b[t * 4], Bh + c * 512 + ((iu ^ (c & 7)) << 4));
            }
#pragma unroll
            for (int mi = 0; mi < 2; mi++)
#pragma unroll
                for (int ni = 0; ni < 8; ni++)
                    mma16816(acc[mi][ni], a[mi], b[(ni >> 1) * 4 + (ni & 1) * 2],
                             b[(ni >> 1) * 4 + (ni & 1) * 2 + 1]);
            // B lo fragments + mma (same A, same accumulators)
#pragma unroll
            for (int t = 0; t < 4; t++) {
                int c = kt + lr + l8;
                int iu = (ib + t * 16 + l16) >> 3;
                ldsm_x4t(&b[t * 4], Bl + c * 512 + ((iu ^ (c & 7)) << 4));
            }
#pragma unroll
            for (int mi = 0; mi < 2; mi++)
#pragma unroll
                for (int ni = 0; ni < 8; ni++)
                    mma16816(acc[mi][ni], a[mi], b[(ni >> 1) * 4 + (ni & 1) * 2],
                             b[(ni >> 1) * 4 + (ni & 1) * 2 + 1]);
        }
        CP_WAIT0();
        __syncthreads();
    }

    // epilogue: partials, deterministic
    int g = lane >> 2, tg = lane & 3;
    float* base = g_part + ((size_t)jg * MROWS) * HDIM;
#pragma unroll
    for (int mi = 0; mi < 2; mi++) {
#pragma unroll
        for (int ni = 0; ni < 8; ni++) {
            int row = m0 + mb + mi * 16 + g;
            int col = ib + ni * 8 + tg * 2;
            *(float2*)&base[(size_t)row * HDIM + col] =
                make_float2(acc[mi][ni][0], acc[mi][ni][1]);
            *(float2*)&base[(size_t)(row + 8) * HDIM + col] =
                make_float2(acc[mi][ni][2], acc[mi][ni][3]);
        }
    }
}

// ---------------- deterministic j-group reduction: out += sum(partials) -------------
__global__ void reduce_kernel(float* __restrict__ out) {
    int i = blockIdx.x * blockDim.x + threadIdx.x;   // float4 units
    float4* o4 = (float4*)out;
    float4 v = o4[i];
    const float4* p4 = (const float4*)g_part;
#pragma unroll
    for (int s = 0; s < JGROUPS; s++) {
        float4 p = p4[(size_t)s * (MROWS * HDIM / 4) + i];
        v.x += p.x; v.y += p.y; v.z += p.z; v.w += p.w;
    }
    o4[i] = v;
}

// ---------------- hidden = output[T-1] ----------------
__global__ void copy_hidden_kernel(float* __restrict__ out) {
    int idx = blockIdx.x * blockDim.x + threadIdx.x;
    out[MROWS * HDIM + idx] = out[(MROWS - BATCH) * HDIM + idx];
}

// ---------------- launch ----------------
extern "C" void kernel_launch(void* const* d_in, const int* in_sizes, int n_in,
                              void* d_out, int out_size) {
    const float* x      = (const float*)d_in[0];
    const float* w_i2h  = (const float*)d_in[1];
    const float* b_i2h  = (const float*)d_in[2];
    // d_in[3]/d_in[4] = w_h2h/b_h2h: dead in the reference (hidden overwritten)
    const float* w_i2c  = (const float*)d_in[5];
    const float* b_i2c  = (const float*)d_in[6];
    const float* w_c2c  = (const float*)d_in[7];
    const float* b_c2c  = (const float*)d_in[8];
    const float* w_c2t  = (const float*)d_in[9];
    const float* b_c2t  = (const float*)d_in[10];
    float* out = (float*)d_out;
    (void)in_sizes; (void)n_in; (void)out_size;

    tvec_kernel<<<(HDIM * HDIM + 255) / 256, 256>>>(w_c2c, 0, HDIM, HDIM);
    tvec_kernel<<<(HDIM * IDIM + 255) / 256, 256>>>(w_i2h, 1, HDIM, IDIM);
    tvec_kernel<<<(HDIM * IDIM + 255) / 256, 256>>>(w_i2c, 2, HDIM, IDIM);
    tvec_kernel<<<(HDIM * HDIM + 255) / 256, 256>>>(b_c2t, 3, HDIM, HDIM);

    cudaFuncSetAttribute(bsplit_kernel,
                         cudaFuncAttributeMaxDynamicSharedMemorySize, 256 * 65 * 4);
    bsplit_kernel<<<1024, 256, 256 * 65 * 4>>>(w_c2t);

    proj_kernel<<<MROWS, HDIM>>>(x, b_i2h, b_i2c);
    bconst_kernel<<<MROWS, HDIM>>>(out);
    ctx_kernel<<<BATCH, HDIM>>>(b_c2c, out + MROWS * HDIM + BATCH * HDIM);

    cudaFuncSetAttribute(hyper_kernel,
                         cudaFuncAttributeMaxDynamicSharedMemorySize, GEMM_SMEM);
    hyper_kernel<<<dim3(MROWS / 128, JGROUPS), 512, GEMM_SMEM>>>();

    reduce_kernel<<<(MROWS * HDIM / 4) / 256, 256>>>(out);
    copy_hidden_kernel<<<(BATCH * HDIM) / 1024, 1024>>>(out);
}

// round 5
// speedup vs baseline: 3.6127x; 1.0405x over previous
#include <cuda_runtime.h>
#include <cuda_fp16.h>
#include <cstdint>

#define T_STEPS 64
#define BATCH   32
#define IDIM    128
#define HDIM    256
#define MROWS   (T_STEPS * BATCH)   // 2048
#define KTOT    65536               // (j,c) contraction
#define JGROUPS 8
#define CHUNKS  128                 // 32 j x 4 c-blocks per CTA

// ---------------- scratch (__device__ globals; no allocations allowed) ----------------
__device__ float  g_ip [MROWS * HDIM];
__device__ float  g_xc [MROWS * HDIM];
__device__ float  g_ctx[MROWS * HDIM];
__device__ float  g_wtv_c2c[HDIM * HDIM];
__device__ float  g_wtv_i2h[HDIM * IDIM];
__device__ float  g_wtv_i2c[HDIM * IDIM];
__device__ float  g_btv    [HDIM * HDIM];
__device__ __half g_bhi[(size_t)HDIM * KTOT];   // pre-swizzled 64-k chunk images (hi only)
__device__ float  g_part[(size_t)JGROUPS * MROWS * HDIM];

// ---------------- small PTX helpers (base ISA only — no "a" features) ----------------
__device__ __forceinline__ uint32_t smem_u32(const void* p) {
    uint32_t a;
    asm("{ .reg .u64 t; cvta.to.shared.u64 t, %1; cvt.u32.u64 %0, t; }" : "=r"(a) : "l"(p));
    return a;
}
__device__ __forceinline__ void cp16(uint32_t dst, const void* src) {
    asm volatile("cp.async.cg.shared.global [%0], [%1], 16;" :: "r"(dst), "l"(src));
}
#define CP_COMMIT() asm volatile("cp.async.commit_group;" ::: "memory")
#define CP_WAIT0()  asm volatile("cp.async.wait_group 0;" ::: "memory")

__device__ __forceinline__ void ldsm_x4(uint32_t* r, uint32_t addr) {
    asm volatile("ldmatrix.sync.aligned.m8n8.x4.shared.b16 {%0,%1,%2,%3}, [%4];"
                 : "=r"(r[0]), "=r"(r[1]), "=r"(r[2]), "=r"(r[3]) : "r"(addr));
}
__device__ __forceinline__ void ldsm_x4t(uint32_t* r, uint32_t addr) {
    asm volatile("ldmatrix.sync.aligned.m8n8.x4.trans.shared.b16 {%0,%1,%2,%3}, [%4];"
                 : "=r"(r[0]), "=r"(r[1]), "=r"(r[2]), "=r"(r[3]) : "r"(addr));
}
__device__ __forceinline__ void mma16816(float* d, const uint32_t* a,
                                         uint32_t b0, uint32_t b1) {
    asm volatile(
        "mma.sync.aligned.m16n8k16.row.col.f32.f16.f16.f32 "
        "{%0,%1,%2,%3},{%4,%5,%6,%7},{%8,%9},{%0,%1,%2,%3};"
        : "+f"(d[0]), "+f"(d[1]), "+f"(d[2]), "+f"(d[3])
        : "r"(a[0]), "r"(a[1]), "r"(a[2]), "r"(a[3]), "r"(b0), "r"(b1));
}
__device__ __forceinline__ uint32_t pkh(__half a, __half b) {
    __half2 p = __halves2half2(a, b);
    return *(uint32_t*)&p;
}
__device__ __forceinline__ uint32_t pkf(float a, float b) {
    __half2 p = __float22half2_rn(make_float2(a, b));
    return *(uint32_t*)&p;
}

// ---------------- all 4 transposes in one launch ----------------
// layout: out[(k>>2)*(HDIM*4) + i*4 + (k&3)] = in[i*K + k]
__global__ void tvec_all_kernel(const float* __restrict__ w_c2c,
                                const float* __restrict__ w_i2h,
                                const float* __restrict__ w_i2c,
                                const float* __restrict__ b_c2t) {
    int blk = blockIdx.x;
    const float* in;
    float* out;
    int K;
    if (blk < 256)        { in = w_c2c; out = g_wtv_c2c; K = HDIM; }
    else if (blk < 384)   { in = w_i2h; out = g_wtv_i2h; K = IDIM; blk -= 256; }
    else if (blk < 512)   { in = w_i2c; out = g_wtv_i2c; K = IDIM; blk -= 384; }
    else                  { in = b_c2t; out = g_btv;     K = HDIM; blk -= 512; }
    int idx = blk * 256 + threadIdx.x;
    int i = idx / K;
    int k = idx - i * K;
    out[(k >> 2) * (HDIM * 4) + i * 4 + (k & 3)] = in[idx];
}

// ---------------- fp16 (hi-only) image of w_c2t as pre-swizzled chunk images --------
// Chunk kc = j*4+cb holds B_chunk[c=0..63][i=0..255] fp16 (32 KB):
//   phys(c,i) = c*512 + (((i>>3) ^ (c&7)) << 4) + (i&7)*2
__global__ void bsplit_kernel(const float* __restrict__ w) {
    extern __shared__ float s[];                // [256][65]
    int kc = blockIdx.x;                        // 0..1023
    int j = kc >> 2, cb = kc & 3;
    int base = j * 256 + cb * 64;
    int tid = threadIdx.x;
    for (int u = tid; u < 256 * 16; u += 256) {
        int i = u >> 4, f = u & 15;
        float4 v = *(const float4*)(w + (size_t)i * KTOT + base + f * 4);
        s[i * 65 + f * 4 + 0] = v.x;
        s[i * 65 + f * 4 + 1] = v.y;
        s[i * 65 + f * 4 + 2] = v.z;
        s[i * 65 + f * 4 + 3] = v.w;
    }
    __syncthreads();
    char* oh = (char*)(g_bhi + (size_t)kc * 16384);
#pragma unroll
    for (int it = 0; it < 8; it++) {
        int u = tid + it * 256;
        int c = u >> 5, ib = u & 31;
        uint32_t ph[4];
#pragma unroll
        for (int e = 0; e < 4; e++) {
            float w0 = s[(ib * 8 + 2 * e + 0) * 65 + c];
            float w1 = s[(ib * 8 + 2 * e + 1) * 65 + c];
            ph[e] = pkh(__float2half_rn(w0), __float2half_rn(w1));
        }
        uint32_t off = c * 512 + ((ib ^ (c & 7)) << 4);
        *(uint4*)(oh + off) = make_uint4(ph[0], ph[1], ph[2], ph[3]);
    }
}

// ---------------- ip / xc projections fused with bconst ----------------
__global__ void projb_kernel(const float* __restrict__ x,
                             const float* __restrict__ b_i2h,
                             const float* __restrict__ b_i2c,
                             float* __restrict__ out) {
    __shared__ float xs[IDIM];
    __shared__ float ips[HDIM];
    int m = blockIdx.x;
    int i = threadIdx.x;
    if (i < IDIM) xs[i] = x[m * IDIM + i];
    __syncthreads();
    float s1 = b_i2h[i];
    float s2 = b_i2c[i];
#pragma unroll
    for (int k4 = 0; k4 < IDIM / 4; k4++) {
        float4 w1 = *(const float4*)&g_wtv_i2h[k4 * (HDIM * 4) + i * 4];
        float4 w2 = *(const float4*)&g_wtv_i2c[k4 * (HDIM * 4) + i * 4];
        float x0 = xs[k4 * 4 + 0], x1 = xs[k4 * 4 + 1];
        float x2 = xs[k4 * 4 + 2], x3 = xs[k4 * 4 + 3];
        s1 += w1.x * x0 + w1.y * x1 + w1.z * x2 + w1.w * x3;
        s2 += w2.x * x0 + w2.y * x1 + w2.z * x2 + w2.w * x3;
    }
    g_ip[m * HDIM + i] = s1;
    g_xc[m * HDIM + i] = s2;
    ips[i] = s1;
    __syncthreads();
    float a0 = 0.f, a1 = 0.f, a2 = 0.f, a3 = 0.f;
#pragma unroll 8
    for (int j4 = 0; j4 < HDIM / 4; j4++) {
        float4 w = *(const float4*)&g_btv[j4 * (HDIM * 4) + i * 4];
        a0 += w.x * ips[j4 * 4 + 0];
        a1 += w.y * ips[j4 * 4 + 1];
        a2 += w.z * ips[j4 * 4 + 2];
        a3 += w.w * ips[j4 * 4 + 3];
    }
    out[m * HDIM + i] = (a0 + a1) + (a2 + a3);
}

// ---------------- context trajectory (4 accumulators to break the FFMA chain) -------
__global__ void ctx_kernel(const float* __restrict__ b_c2c,
                           float* __restrict__ out_ctx_final) {
    __shared__ float cs[HDIM];
    int b = blockIdx.x;
    int i = threadIdx.x;
    const float a = 0.2f;
    const float one_minus_a = 1.0f - a;
    cs[i] = 0.f;
    __syncthreads();
    for (int t = 0; t < T_STEPS; t++) {
        g_ctx[(t * BATCH + b) * HDIM + i] = cs[i];
        float s0 = b_c2c[i] + g_xc[(t * BATCH + b) * HDIM + i];
        float s1 = 0.f, s2 = 0.f, s3 = 0.f;
#pragma unroll 8
        for (int c4 = 0; c4 < HDIM / 4; c4++) {
            float4 w = *(const float4*)&g_wtv_c2c[c4 * (HDIM * 4) + i * 4];
            float4 cv = *(const float4*)&cs[c4 * 4];
            s0 += w.x * cv.x;
            s1 += w.y * cv.y;
            s2 += w.z * cv.z;
            s3 += w.w * cv.w;
        }
        float s = fmaxf((s0 + s1) + (s2 + s3), 0.f);
        float nc = one_minus_a * cs[i] + a * s;
        __syncthreads();
        cs[i] = nc;
        __syncthreads();
    }
    out_ctx_final[b * HDIM + i] = cs[i];
}

// ---------------- mma.sync hypernet GEMM (single pass, W-hi only) ----------------
// out[m,i] = sum_{j,c} half(ip[m,j]*ctx[m,c]) * Whi[i, j*256+c]
// CTA: 128 m x 256 i, j-group of 32 (K=8192), 512 threads (4x4 warps, 32m x 64i each).
// Stage: A = 128m x 64c fp16 = 16 KB; B = 64c x 256i fp16 = 32 KB  -> 48 KB/stage.
#define A_OFF   0
#define B_OFF   16384
#define STAGE   49152
#define GEMM_SMEM (2 * STAGE)      // 98304 B

// phys addr inside A stage: m*128 + ((c/8 ^ m%8)<<4) + (c%8)*2
// phys addr inside B stage: c*512 + ((i/8 ^ c%8)<<4) + (i%8)*2

__device__ __forceinline__ void produce_chunk(char* sm, uint32_t smb, int s,
                                              int nc, int m0, int jg) {
    uint32_t base_u = smb + s * STAGE;
    char*    base_p = sm + s * STAGE;
    int tid = threadIdx.x;
    int jl = nc >> 2, cb = nc & 3;
    int j = jg * 32 + jl;
    const char* srch = (const char*)(g_bhi + (size_t)(j * 4 + cb) * 16384);
#pragma unroll
    for (int it = 0; it < 4; it++) {            // 4 x 512 x 16 B = 32 KB (full chunk)
        int u = tid + it * 512;
        cp16(base_u + B_OFF + u * 16, srch + (size_t)u * 16);
    }
    CP_COMMIT();

    // A: 128 m x 64 c; thread -> (m = tid/4, 16 c's at q*16); fp32 product, single rounding
    int m = tid >> 2, q = tid & 3;
    int row = m0 + m;
    float ip = g_ip[row * HDIM + j];
    const float* cp = &g_ctx[row * HDIM + cb * 64 + q * 16];
    uint32_t p[8];
#pragma unroll
    for (int e = 0; e < 4; e++) {
        float4 cv = *(const float4*)(cp + e * 4);
        p[e * 2 + 0] = pkf(ip * cv.x, ip * cv.y);
        p[e * 2 + 1] = pkf(ip * cv.z, ip * cv.w);
    }
    char* arow = base_p + A_OFF + m * 128;
    int sw = m & 7;
    *(uint4*)(arow + (((q * 2 + 0) ^ sw) << 4)) = make_uint4(p[0], p[1], p[2], p[3]);
    *(uint4*)(arow + (((q * 2 + 1) ^ sw) << 4)) = make_uint4(p[4], p[5], p[6], p[7]);
}

__global__ void __launch_bounds__(512, 1)
hyper_kernel() {
    extern __shared__ char sm[];
    uint32_t smb = smem_u32(sm);
    int tid = threadIdx.x;
    int lane = tid & 31, wid = tid >> 5;
    int warp_m = wid >> 2, warp_i = wid & 3;     // 4 x 4
    int mb = warp_m * 32, ib = warp_i * 64;
    const int m0 = blockIdx.x * 128;
    const int jg = blockIdx.y;

    float acc[2][8][4];
#pragma unroll
    for (int a = 0; a < 2; a++)
#pragma unroll
        for (int b = 0; b < 8; b++)
#pragma unroll
            for (int c = 0; c < 4; c++) acc[a][b][c] = 0.f;

    int lr  = lane & 7;
    int l8  = lane & 8;
    int l16 = (lane & 16) ? 8 : 0;

    produce_chunk(sm, smb, 0, 0, m0, jg);
    CP_WAIT0();
    __syncthreads();

    for (int nc = 0; nc < CHUNKS; nc++) {
        int s = nc & 1;
        if (nc + 1 < CHUNKS) produce_chunk(sm, smb, s ^ 1, nc + 1, m0, jg);

        uint32_t Ab = smb + s * STAGE + A_OFF;
        uint32_t Bb = smb + s * STAGE + B_OFF;

#pragma unroll
        for (int kt = 0; kt < 64; kt += 16) {
            uint32_t a[2][4];
#pragma unroll
            for (int mi = 0; mi < 2; mi++) {
                int mrow = mb + mi * 16 + lr + l8;
                uint32_t ad = Ab + mrow * 128 + (((((kt + l16) >> 3)) ^ (mrow & 7)) << 4);
                ldsm_x4(a[mi], ad);
            }
            uint32_t b[16];
#pragma unroll
            for (int t = 0; t < 4; t++) {
                int c = kt + lr + l8;
                int iu = (ib + t * 16 + l16) >> 3;
                ldsm_x4t(&b[t * 4], Bb + c * 512 + ((iu ^ (c & 7)) << 4));
            }
#pragma unroll
            for (int mi = 0; mi < 2; mi++)
#pragma unroll
                for (int ni = 0; ni < 8; ni++)
                    mma16816(acc[mi][ni], a[mi], b[(ni >> 1) * 4 + (ni & 1) * 2],
                             b[(ni >> 1) * 4 + (ni & 1) * 2 + 1]);
        }
        CP_WAIT0();
        __syncthreads();
    }

    int g = lane >> 2, tg = lane & 3;
    float* base = g_part + ((size_t)jg * MROWS) * HDIM;
#pragma unroll
    for (int mi = 0; mi < 2; mi++) {
#pragma unroll
        for (int ni = 0; ni < 8; ni++) {
            int row = m0 + mb + mi * 16 + g;
            int col = ib + ni * 8 + tg * 2;
            *(float2*)&base[(size_t)row * HDIM + col] =
                make_float2(acc[mi][ni][0], acc[mi][ni][1]);
            *(float2*)&base[(size_t)(row + 8) * HDIM + col] =
                make_float2(acc[mi][ni][2], acc[mi][ni][3]);
        }
    }
}

// ---------------- deterministic j-group reduction: out += sum(partials) -------------
__global__ void reduce_kernel(float* __restrict__ out) {
    int i = blockIdx.x * blockDim.x + threadIdx.x;   // float4 units
    float4* o4 = (float4*)out;
    float4 v = o4[i];
    const float4* p4 = (const float4*)g_part;
#pragma unroll
    for (int s = 0; s < JGROUPS; s++) {
        float4 p = p4[(size_t)s * (MROWS * HDIM / 4) + i];
        v.x += p.x; v.y += p.y; v.z += p.z; v.w += p.w;
    }
    o4[i] = v;
}

// ---------------- hidden = output[T-1] ----------------
__global__ void copy_hidden_kernel(float* __restrict__ out) {
    int idx = blockIdx.x * blockDim.x + threadIdx.x;
    out[MROWS * HDIM + idx] = out[(MROWS - BATCH) * HDIM + idx];
}

// ---------------- launch ----------------
extern "C" void kernel_launch(void* const* d_in, const int* in_sizes, int n_in,
                              void* d_out, int out_size) {
    const float* x      = (const float*)d_in[0];
    const float* w_i2h  = (const float*)d_in[1];
    const float* b_i2h  = (const float*)d_in[2];
    // d_in[3]/d_in[4] = w_h2h/b_h2h: dead in the reference (hidden overwritten)
    const float* w_i2c  = (const float*)d_in[5];
    const float* b_i2c  = (const float*)d_in[6];
    const float* w_c2c  = (const float*)d_in[7];
    const float* b_c2c  = (const float*)d_in[8];
    const float* w_c2t  = (const float*)d_in[9];
    const float* b_c2t  = (const float*)d_in[10];
    float* out = (float*)d_out;
    (void)in_sizes; (void)n_in; (void)out_size;

    tvec_all_kernel<<<768, 256>>>(w_c2c, w_i2h, w_i2c, b_c2t);

    cudaFuncSetAttribute(bsplit_kernel,
                         cudaFuncAttributeMaxDynamicSharedMemorySize, 256 * 65 * 4);
    bsplit_kernel<<<1024, 256, 256 * 65 * 4>>>(w_c2t);

    projb_kernel<<<MROWS, HDIM>>>(x, b_i2h, b_i2c, out);
    ctx_kernel<<<BATCH, HDIM>>>(b_c2c, out + MROWS * HDIM + BATCH * HDIM);

    cudaFuncSetAttribute(hyper_kernel,
                         cudaFuncAttributeMaxDynamicSharedMemorySize, GEMM_SMEM);
    hyper_kernel<<<dim3(MROWS / 128, JGROUPS), 512, GEMM_SMEM>>>();

    reduce_kernel<<<(MROWS * HDIM / 4) / 256, 256>>>(out);
    copy_hidden_kernel<<<(BATCH * HDIM) / 1024, 1024>>>(out);
}